// round 14
// baseline (speedup 1.0000x reference)
#include <cuda_runtime.h>
#include <cuda_fp16.h>
#include <cstdint>

#define BATCH 65536
#define RSA64 144  // A smem row: 64 halfs (128B) + 16B pad
#define RSA 80     // expert A smem row: 32 halfs + 16B pad
#define RSG 528    // g smem row: 256 halfs (512B) + 16B pad

// ---------------- scratch (device globals; no allocation allowed) ----------
__device__ __half g_obsh[(size_t)BATCH * 512];
__device__ __half g_h0s0[(size_t)BATCH * 1280];   // [h0 | s0] packed
__device__ __half g_h1[(size_t)BATCH * 1024];
__device__ __half g_h2[(size_t)BATCH * 512];
__device__ __half g_s1[(size_t)BATCH * 128];
__device__ float  g_w [(size_t)BATCH * 16];
__device__ float  g_rb[(size_t)BATCH * 32];
__device__ float  g_part[(size_t)16 * BATCH * 32];
// fp16 weights (converted once per replay; deterministic)
__device__ __half g_W0cat[512 * 1280];            // [Wb0 | Ws0]
__device__ float  g_b0cat[1280];
__device__ __half g_Wb1h[1024 * 1024];
__device__ __half g_Wb2h[1024 * 512];
__device__ __half g_Ws1h[256 * 128];
__device__ __half g_We1h[16 * 512 * 256];
__device__ __half g_We2h[4096 * 32];

// ---------------- helpers ---------------------------------------------------
__device__ __forceinline__ uint32_t smem_u32(const void* p) {
    uint32_t a;
    asm("{ .reg .u64 t; cvta.to.shared.u64 t, %1; cvt.u32.u64 %0, t; }" : "=r"(a) : "l"(p));
    return a;
}
__device__ __forceinline__ void mma_f16(float* d, const uint32_t* a, uint32_t b0, uint32_t b1) {
    asm volatile(
        "mma.sync.aligned.m16n8k16.row.col.f32.f16.f16.f32 "
        "{%0,%1,%2,%3}, {%4,%5,%6,%7}, {%8,%9}, {%0,%1,%2,%3};\n"
        : "+f"(d[0]), "+f"(d[1]), "+f"(d[2]), "+f"(d[3])
        : "r"(a[0]), "r"(a[1]), "r"(a[2]), "r"(a[3]), "r"(b0), "r"(b1));
}
#define LDSM_X4(r, addr) \
    asm volatile("ldmatrix.sync.aligned.m8n8.x4.shared.b16 {%0,%1,%2,%3}, [%4];" \
        : "=r"((r)[0]), "=r"((r)[1]), "=r"((r)[2]), "=r"((r)[3]) : "r"(addr))
#define LDSM_X4_T(r, addr) \
    asm volatile("ldmatrix.sync.aligned.m8n8.x4.trans.shared.b16 {%0,%1,%2,%3}, [%4];" \
        : "=r"((r)[0]), "=r"((r)[1]), "=r"((r)[2]), "=r"((r)[3]) : "r"(addr))
#define CP_ASYNC16(dst, src) \
    asm volatile("cp.async.cg.shared.global [%0], [%1], 16;\n" :: "r"(dst), "l"(src))
#define CP_COMMIT() asm volatile("cp.async.commit_group;\n" ::: "memory")
#define CP_WAIT1()  asm volatile("cp.async.wait_group 1;\n" ::: "memory")
#define CP_WAIT0()  asm volatile("cp.async.wait_group 0;\n" ::: "memory")

__device__ __forceinline__ uint32_t packh2(float lo, float hi) {
    __half2 h = __floats2half2_rn(lo, hi);
    return *(uint32_t*)&h;
}

// ---------------- fp32 -> fp16 conversion (8 elems/thread) ------------------
__global__ __launch_bounds__(256) void f2h_kernel(
    const float* __restrict__ src, __half* __restrict__ dst, size_t n8)
{
    size_t i = (size_t)blockIdx.x * 256 + threadIdx.x;
    if (i >= n8) return;
    float4 a = ((const float4*)src)[2 * i];
    float4 b = ((const float4*)src)[2 * i + 1];
    uint4 u;
    u.x = packh2(a.x, a.y); u.y = packh2(a.z, a.w);
    u.z = packh2(b.x, b.y); u.w = packh2(b.z, b.w);
    ((uint4*)dst)[i] = u;
}

// ---------------- concat-convert: W0cat = [Wb0 | Ws0] fp16, b0cat -----------
__global__ __launch_bounds__(256) void cat_kernel(
    const float* __restrict__ Wb0, const float* __restrict__ Ws0,
    const float* __restrict__ bb0, const float* __restrict__ bs0,
    __half* __restrict__ Wcat, float* __restrict__ bcat)
{
    size_t i = (size_t)blockIdx.x * 256 + threadIdx.x;
    if (i < (size_t)512 * 1280) {
        int k = (int)(i / 1280), c = (int)(i % 1280);
        float v = (c < 1024) ? Wb0[(size_t)k * 1024 + c] : Ws0[(size_t)k * 256 + (c - 1024)];
        Wcat[i] = __float2half_rn(v);
    }
    if (i < 1280) bcat[i] = (i < 1024) ? bb0[i] : bs0[i - 1024];
}

// ---------------- generic GEMM: C(half) = act(A @ B + bias) -----------------
// 128 x 128 block, 128 thr, 4 warps (2x2), warp tile 64x64, BK=64.
// 3-stage cp.async pipeline, hoisted ldmatrix per 32-k sub-chunk, 2 CTAs/SM.
template<bool RELU>
__global__ __launch_bounds__(128, 2) void tc_gemm(
    const __half* __restrict__ A, const __half* __restrict__ B,
    const float* __restrict__ bias, __half* __restrict__ C,
    int K, int N, int lda)
{
    extern __shared__ char smem[];
    constexpr int BN  = 128;
    constexpr int RSB = BN * 2 + 16;           // 272
    constexpr int ASZ = 128 * RSA64;           // 18432
    constexpr int STG = ASZ + 64 * RSB;        // 35840
    constexpr int NF  = 8;
    float* sbias = (float*)(smem + 3 * STG);

    const int tid = threadIdx.x, warp = tid >> 5, lane = tid & 31;
    const int rA = (warp >> 1) * 64, cB = (warp & 1) * 64;
    const int lg = lane >> 2, lt = lane & 3;
    const int m0 = blockIdx.y * 128, n0 = blockIdx.x * BN;

    const __half* Bp = B + n0;

    if (tid < BN) sbias[tid] = bias[n0 + tid];

    const uint32_t smb = smem_u32(smem);
    const int li = lane & 7, ls = lane >> 3;
    const uint32_t aOff = (uint32_t)(rA + li + 8 * (ls & 1)) * RSA64 + (ls >> 1) * 16;
    const uint32_t bOff = ASZ + (uint32_t)(li + 8 * (ls & 1)) * RSB
                        + (uint32_t)(cB + 8 * (ls >> 1)) * 2;

    float acc[4][NF][4];
#pragma unroll
    for (int i = 0; i < 4; i++)
#pragma unroll
        for (int j = 0; j < NF; j++)
#pragma unroll
            for (int k = 0; k < 4; k++) acc[i][j][k] = 0.f;

    const int NT = K >> 6;   // 64-deep k-tiles

#define LOAD_STAGE(t, buf)                                                     \
    {                                                                          \
        const uint32_t base = smb + (buf) * STG;                               \
        const int k0 = (t) * 64;                                               \
        _Pragma("unroll")                                                      \
        for (int j = 0; j < 8; j++) {                                          \
            int i = tid + 128 * j;                                             \
            int r = i >> 3, q = i & 7;                                         \
            CP_ASYNC16(base + r * RSA64 + q * 16,                              \
                       A + (size_t)(m0 + r) * lda + k0 + q * 8);               \
        }                                                                      \
        _Pragma("unroll")                                                      \
        for (int j = 0; j < 8; j++) {                                          \
            int i = tid + 128 * j;                                             \
            int krow = i >> 4, c16 = i & 15;                                   \
            CP_ASYNC16(base + ASZ + krow * RSB + c16 * 16,                     \
                       Bp + (size_t)(k0 + krow) * N + c16 * 8);                \
        }                                                                      \
        CP_COMMIT();                                                           \
    }

    LOAD_STAGE(0, 0);
    LOAD_STAGE(1, 1);

    int buf = 0, nbuf = 2;
    for (int t = 0; t < NT; t++) {
        if (t + 1 < NT) { CP_WAIT1(); } else { CP_WAIT0(); }
        __syncthreads();
        if (t + 2 < NT) { LOAD_STAGE(t + 2, nbuf); }

        const uint32_t base = smb + buf * STG;
#pragma unroll
        for (int sub = 0; sub < 2; sub++) {
            uint32_t a[2][4][4];
            uint32_t b[2][NF / 2][4];
#pragma unroll
            for (int h = 0; h < 2; h++) {
#pragma unroll
                for (int mf = 0; mf < 4; mf++)
                    LDSM_X4(a[h][mf], base + aOff + mf * (16 * RSA64) + sub * 64 + h * 32);
#pragma unroll
                for (int nfp = 0; nfp < NF / 2; nfp++)
                    LDSM_X4_T(b[h][nfp], base + bOff + nfp * 32
                              + (sub * 2 + h) * (16 * RSB));
            }
#pragma unroll
            for (int h = 0; h < 2; h++)
#pragma unroll
                for (int mf = 0; mf < 4; mf++)
#pragma unroll
                    for (int nf = 0; nf < NF; nf++)
                        mma_f16(acc[mf][nf], a[h][mf],
                                b[h][nf >> 1][(nf & 1) * 2], b[h][nf >> 1][(nf & 1) * 2 + 1]);
        }
        // no trailing barrier: 3-stage ring; load(t+2) hits buffer (t-1)%3,
        // ordered by this iteration's top-of-loop barrier.
        buf = (buf == 2) ? 0 : buf + 1;
        nbuf = (nbuf == 2) ? 0 : nbuf + 1;
    }
#undef LOAD_STAGE

#pragma unroll
    for (int mf = 0; mf < 4; mf++) {
        int row = m0 + rA + mf * 16 + lg;
#pragma unroll
        for (int nf = 0; nf < NF; nf++) {
            int cl = cB + nf * 8 + lt * 2;
            int col = n0 + cl;
            float b0 = sbias[cl], b1 = sbias[cl + 1];
            float v0 = acc[mf][nf][0] + b0, v1 = acc[mf][nf][1] + b1;
            float v2 = acc[mf][nf][2] + b0, v3 = acc[mf][nf][3] + b1;
            if (RELU) {
                v0 = fmaxf(v0, 0.f); v1 = fmaxf(v1, 0.f);
                v2 = fmaxf(v2, 0.f); v3 = fmaxf(v3, 0.f);
            }
            *(uint32_t*)(C + (size_t)row * N + col)       = packh2(v0, v1);
            *(uint32_t*)(C + (size_t)(row + 8) * N + col) = packh2(v2, v3);
        }
    }
}

// ---------------- fused expert kernel (R9 proven shape: 256 thr, BN=256) ----
__global__ __launch_bounds__(256, 1) void expert_gemm(
    const __half* __restrict__ A, const __half* __restrict__ We1,
    const float* __restrict__ be1, const float* __restrict__ wsel,
    const __half* __restrict__ We2, float* __restrict__ part)
{
    extern __shared__ char smem[];
    constexpr int BN = 256, K = 512;
    constexpr int RSB = BN * 2 + 16;
    constexpr int ASZ = 128 * RSA;
    constexpr int STG = ASZ + 32 * RSB;
    constexpr int CPR = BN / 8;
    constexpr int NF  = 8;
    constexpr int GBUF = 0;
    constexpr int W2S  = 128 * RSG;
    float* sbias = (float*)(smem + 3 * STG);

    const int tid = threadIdx.x, warp = tid >> 5, lane = tid & 31;
    const int rA = (warp >> 2) * 64, cB = (warp & 3) * 64;
    const int lg = lane >> 2, lt = lane & 3;
    const int m0 = blockIdx.y * 128;
    const int e  = blockIdx.x;

    const __half* Bp = We1 + (size_t)e * K * 256;

    for (int i = tid; i < BN; i += 256) sbias[i] = be1[e * 256 + i];

    const uint32_t smb = smem_u32(smem);
    const int li = lane & 7, ls = lane >> 3;
    const uint32_t aOff = (uint32_t)(rA + li + 8 * (ls & 1)) * RSA + (ls >> 1) * 16;
    const uint32_t bOff = ASZ + (uint32_t)(li + 8 * (ls & 1)) * RSB
                        + (uint32_t)(cB + 8 * (ls >> 1)) * 2;

    float acc[4][NF][4];
#pragma unroll
    for (int i = 0; i < 4; i++)
#pragma unroll
        for (int j = 0; j < NF; j++)
#pragma unroll
            for (int k = 0; k < 4; k++) acc[i][j][k] = 0.f;

    const int NT = K >> 5;

#define LOAD_STAGE(t, bufi)                                                    \
    {                                                                          \
        const uint32_t base = smb + (bufi) * STG;                              \
        const int k0 = (t) * 32;                                               \
        _Pragma("unroll")                                                      \
        for (int j = 0; j < 2; j++) {                                          \
            int i = tid + 256 * j;                                             \
            int r = i >> 2, q = i & 3;                                         \
            CP_ASYNC16(base + r * RSA + q * 16,                                \
                       A + (size_t)(m0 + r) * K + k0 + q * 8);                 \
        }                                                                      \
        _Pragma("unroll")                                                      \
        for (int j = 0; j < 4; j++) {                                          \
            int i = tid + 256 * j;                                             \
            int krow = i / CPR, c16 = i % CPR;                                 \
            CP_ASYNC16(base + ASZ + krow * RSB + c16 * 16,                     \
                       Bp + (size_t)(k0 + krow) * 256 + c16 * 8);              \
        }                                                                      \
        CP_COMMIT();                                                           \
    }

    LOAD_STAGE(0, 0);
    LOAD_STAGE(1, 1);

    int buf = 0, nbuf = 2;
    for (int t = 0; t < NT; t++) {
        if (t + 1 < NT) { CP_WAIT1(); } else { CP_WAIT0(); }
        __syncthreads();
        if (t + 2 < NT) { LOAD_STAGE(t + 2, nbuf); }

        const uint32_t base = smb + buf * STG;
        uint32_t a[2][4][4];
        uint32_t b[2][4][4];
#pragma unroll
        for (int h = 0; h < 2; h++) {
#pragma unroll
            for (int mf = 0; mf < 4; mf++)
                LDSM_X4(a[h][mf], base + aOff + mf * (16 * RSA) + h * 32);
#pragma unroll
            for (int nfp = 0; nfp < 4; nfp++)
                LDSM_X4_T(b[h][nfp], base + bOff + nfp * 32 + h * (16 * RSB));
        }
#pragma unroll
        for (int h = 0; h < 2; h++)
#pragma unroll
            for (int mf = 0; mf < 4; mf++)
#pragma unroll
                for (int nf = 0; nf < NF; nf++)
                    mma_f16(acc[mf][nf], a[h][mf],
                            b[h][nf >> 1][(nf & 1) * 2], b[h][nf >> 1][(nf & 1) * 2 + 1]);
        buf = (buf == 2) ? 0 : buf + 1;
        nbuf = (nbuf == 2) ? 0 : nbuf + 1;
    }
#undef LOAD_STAGE

    __syncthreads();   // epilogue overlays stage buffers

    // ---- epilogue 1: bias + relu + w-scale, pack g into smem ----
#pragma unroll
    for (int mf = 0; mf < 4; mf++) {
        int row = m0 + rA + mf * 16 + lg;
        int lr0 = rA + mf * 16 + lg;
        float ws0 = wsel[(size_t)row * 16 + e];
        float ws1 = wsel[(size_t)(row + 8) * 16 + e];
#pragma unroll
        for (int nf = 0; nf < NF; nf++) {
            int cl = cB + nf * 8 + lt * 2;
            float b0 = sbias[cl], b1 = sbias[cl + 1];
            float v0 = fmaxf(acc[mf][nf][0] + b0, 0.f) * ws0;
            float v1 = fmaxf(acc[mf][nf][1] + b1, 0.f) * ws0;
            float v2 = fmaxf(acc[mf][nf][2] + b0, 0.f) * ws1;
            float v3 = fmaxf(acc[mf][nf][3] + b1, 0.f) * ws1;
            *(uint32_t*)(smem + GBUF + lr0 * RSG + cl * 2)       = packh2(v0, v1);
            *(uint32_t*)(smem + GBUF + (lr0 + 8) * RSG + cl * 2) = packh2(v2, v3);
        }
    }

    // ---- load We2[e] (256x32 half) into smem ----
#pragma unroll
    for (int j = 0; j < 4; j++) {
        int i = tid + 256 * j;
        int hrow = i >> 2, q = i & 3;
        uint4 u = *(const uint4*)(We2 + ((size_t)e * 256 + hrow) * 32 + q * 8);
        *(uint4*)(smem + W2S + hrow * RSA + q * 16) = u;
    }
    __syncthreads();

    // ---- mini-GEMM: part_tile = g(128x256) @ We2s(256x32) ----
    {
        const uint32_t aAddr2 = smb + GBUF
            + (uint32_t)(warp * 16 + li + 8 * (ls & 1)) * RSG + (ls >> 1) * 16;
        const uint32_t bAddr2 = smb + W2S
            + (uint32_t)(li + 8 * (ls & 1)) * RSA + (uint32_t)(8 * (ls >> 1)) * 2;

        float acc2[4][4];
#pragma unroll
        for (int nf = 0; nf < 4; nf++)
#pragma unroll
            for (int k = 0; k < 4; k++) acc2[nf][k] = 0.f;

#pragma unroll
        for (int ks = 0; ks < 16; ks++) {
            uint32_t a[4];
            LDSM_X4(a, aAddr2 + ks * 32);
            uint32_t b[2][4];
#pragma unroll
            for (int nfp = 0; nfp < 2; nfp++)
                LDSM_X4_T(b[nfp], bAddr2 + nfp * 32 + ks * (16 * RSA));
#pragma unroll
            for (int nf = 0; nf < 4; nf++)
                mma_f16(acc2[nf], a, b[nf >> 1][(nf & 1) * 2], b[nf >> 1][(nf & 1) * 2 + 1]);
        }

        float* P = part + (size_t)e * ((size_t)BATCH * 32);
        int row = m0 + warp * 16 + lg;
#pragma unroll
        for (int nf = 0; nf < 4; nf++) {
            int col = nf * 8 + lt * 2;
            *(float2*)(P + (size_t)row * 32 + col)       = make_float2(acc2[nf][0], acc2[nf][1]);
            *(float2*)(P + (size_t)(row + 8) * 32 + col) = make_float2(acc2[nf][2], acc2[nf][3]);
        }
    }
}

// ---------------- selector logits + softmax + fused row bias ----------------
__global__ __launch_bounds__(256) void selector_kernel(
    const __half* __restrict__ s1, const float* __restrict__ Ws2,
    const float* __restrict__ bs2, const float* __restrict__ be2,
    float* __restrict__ wout, float* __restrict__ rbout)
{
    __shared__ float Wsm[128 * 16];
    __shared__ float bsm[16];
    __shared__ float be2s[16 * 32];
    const int tid = threadIdx.x;
    for (int i = tid; i < 2048; i += 256) Wsm[i] = Ws2[i];
    for (int i = tid; i < 512; i += 256) be2s[i] = be2[i];
    if (tid < 16) bsm[tid] = bs2[tid];
    __syncthreads();

    const int warp = tid >> 5, lane = tid & 31;
    const int row = blockIdx.x * 8 + warp;

    float v[4];
#pragma unroll
    for (int j = 0; j < 4; j++)
        v[j] = __half2float(s1[(size_t)row * 128 + j * 32 + lane]);

    float mylog = -1e30f;
#pragma unroll
    for (int e = 0; e < 16; e++) {
        float p = 0.f;
#pragma unroll
        for (int j = 0; j < 4; j++) p += v[j] * Wsm[(j * 32 + lane) * 16 + e];
#pragma unroll
        for (int off = 16; off >= 1; off >>= 1)
            p += __shfl_xor_sync(0xffffffffu, p, off);
        if (lane == e) mylog = p + bsm[e];
    }
    float m = mylog;
#pragma unroll
    for (int off = 8; off >= 1; off >>= 1)
        m = fmaxf(m, __shfl_xor_sync(0xffffffffu, m, off, 16));
    float ex = __expf(mylog - m);
    float s = ex;
#pragma unroll
    for (int off = 8; off >= 1; off >>= 1)
        s += __shfl_xor_sync(0xffffffffu, s, off, 16);
    float wv = ex / s;
    if (lane < 16) wout[(size_t)row * 16 + lane] = wv;

    float rbv = 0.f;
#pragma unroll
    for (int e = 0; e < 16; e++) {
        float we = __shfl_sync(0xffffffffu, wv, e);
        rbv += we * be2s[e * 32 + lane];
    }
    rbout[(size_t)row * 32 + lane] = rbv;
}

// ---------------- 16-way partial reduce + row-bias --------------------------
__global__ __launch_bounds__(256) void reduce_final(
    const float* __restrict__ part, const float* __restrict__ rb,
    float* __restrict__ out)
{
    size_t idx = (size_t)blockIdx.x * 256 + threadIdx.x;
    const size_t S = (size_t)BATCH * 32 / 4;
    const float4* p4 = (const float4*)part;
    float4 r = ((const float4*)rb)[idx];
#pragma unroll
    for (int s = 0; s < 16; s++) {
        float4 p = p4[s * S + idx];
        r.x += p.x; r.y += p.y; r.z += p.z; r.w += p.w;
    }
    ((float4*)out)[idx] = r;
}

// ---------------- launch -----------------------------------------------------
extern "C" void kernel_launch(void* const* d_in, const int* in_sizes, int n_in,
                              void* d_out, int out_size)
{
    const float* obs = (const float*)d_in[0];
    const float* Wb0 = (const float*)d_in[1];  const float* bb0 = (const float*)d_in[2];
    const float* Wb1 = (const float*)d_in[3];  const float* bb1 = (const float*)d_in[4];
    const float* Wb2 = (const float*)d_in[5];  const float* bb2 = (const float*)d_in[6];
    const float* We1 = (const float*)d_in[7];  const float* be1 = (const float*)d_in[8];
    const float* We2 = (const float*)d_in[9];  const float* be2 = (const float*)d_in[10];
    const float* Ws0 = (const float*)d_in[11]; const float* bs0 = (const float*)d_in[12];
    const float* Ws1 = (const float*)d_in[13]; const float* bs1 = (const float*)d_in[14];
    const float* Ws2 = (const float*)d_in[15]; const float* bs2 = (const float*)d_in[16];
    float* out = (float*)d_out;

    __half *obsh, *h0s0, *h1, *h2, *s1;
    __half *W0cat, *Wb1h, *Wb2h, *Ws1h, *We1h, *We2h;
    float *b0cat, *w, *rb, *part;
    cudaGetSymbolAddress((void**)&obsh, g_obsh);
    cudaGetSymbolAddress((void**)&h0s0, g_h0s0);
    cudaGetSymbolAddress((void**)&h1, g_h1);
    cudaGetSymbolAddress((void**)&h2, g_h2);
    cudaGetSymbolAddress((void**)&s1, g_s1);
    cudaGetSymbolAddress((void**)&w,  g_w);
    cudaGetSymbolAddress((void**)&rb, g_rb);
    cudaGetSymbolAddress((void**)&part, g_part);
    cudaGetSymbolAddress((void**)&W0cat, g_W0cat);
    cudaGetSymbolAddress((void**)&b0cat, g_b0cat);
    cudaGetSymbolAddress((void**)&Wb1h, g_Wb1h);
    cudaGetSymbolAddress((void**)&Wb2h, g_Wb2h);
    cudaGetSymbolAddress((void**)&Ws1h, g_Ws1h);
    cudaGetSymbolAddress((void**)&We1h, g_We1h);
    cudaGetSymbolAddress((void**)&We2h, g_We2h);

    constexpr int STG = 128 * RSA64 + 64 * 272;             // 35840
    constexpr int SMG = 3 * STG + 512;                      // 108032 (2 CTAs/SM)
    cudaFuncSetAttribute((const void*)tc_gemm<true>,
                         cudaFuncAttributeMaxDynamicSharedMemorySize, SMG);
    cudaFuncSetAttribute((const void*)expert_gemm,
                         cudaFuncAttributeMaxDynamicSharedMemorySize, 90112);

    auto cvt = [](const float* s, __half* d, size_t n) {
        size_t n8 = n / 8;
        f2h_kernel<<<(unsigned)((n8 + 255) / 256), 256>>>(s, d, n8);
    };
    cvt(obs, obsh, (size_t)BATCH * 512);
    cat_kernel<<<(512 * 1280 + 255) / 256, 256>>>(Wb0, Ws0, bb0, bs0, W0cat, b0cat);
    cvt(Wb1, Wb1h, 1024 * 1024);
    cvt(Wb2, Wb2h, 1024 * 512);
    cvt(Ws1, Ws1h, 256 * 128);
    cvt(We1, We1h, 16 * 512 * 256);
    cvt(We2, We2h, 4096 * 32);

    const int MB = BATCH / 128;   // 512

    // fused backbone-L0 + selector-S0: [B,512] @ [512,1280] -> [h0 | s0]
    tc_gemm<true><<<dim3(10, MB), 128, SMG>>>(obsh, W0cat, b0cat, h0s0, 512, 1280, 512);

    // selector chain
    tc_gemm<true><<<dim3(1, MB), 128, SMG>>>(h0s0 + 1024, Ws1h, bs1, s1, 256, 128, 1280);
    selector_kernel<<<BATCH / 8, 256>>>(s1, Ws2, bs2, be2, w, rb);

    // backbone
    tc_gemm<true><<<dim3(8, MB), 128, SMG>>>(h0s0, Wb1h, bb1, h1, 1024, 1024, 1280);
    tc_gemm<true><<<dim3(4, MB), 128, SMG>>>(h1, Wb2h, bb2, h2, 1024, 512, 1024);

    // fused experts (R9 proven shape)
    expert_gemm<<<dim3(16, MB), 256, 90112>>>(h2, We1h, be1, w, We2h, part);

    // final reduce
    reduce_final<<<(BATCH * 32 / 4) / 256, 256>>>(part, rb, out);
}

// round 15
// speedup vs baseline: 1.1099x; 1.1099x over previous
#include <cuda_runtime.h>
#include <cuda_fp16.h>
#include <cstdint>

#define BATCH 65536
#define RSA 80     // A smem row: 32 halfs (64B) + 16B pad
#define RSG 528    // g smem row: 256 halfs (512B) + 16B pad

// ---------------- scratch (device globals; no allocation allowed) ----------
__device__ __half g_obsh[(size_t)BATCH * 512];
__device__ __half g_h0s0[(size_t)BATCH * 1280];   // [h0 | s0] packed
__device__ __half g_h1[(size_t)BATCH * 1024];
__device__ __half g_h2[(size_t)BATCH * 512];
__device__ float  g_w [(size_t)BATCH * 16];
__device__ float  g_rb[(size_t)BATCH * 32];
__device__ float  g_part[(size_t)16 * BATCH * 32];
// fp16 weights (converted once per replay; deterministic)
__device__ __half g_W0cat[512 * 1280];            // [Wb0 | Ws0]
__device__ float  g_b0cat[1280];
__device__ __half g_Wb1h[1024 * 1024];
__device__ __half g_Wb2h[1024 * 512];
__device__ __half g_Ws1h[256 * 128];
__device__ __half g_We1h[16 * 512 * 256];
__device__ __half g_We2h[4096 * 32];

// ---------------- helpers ---------------------------------------------------
__device__ __forceinline__ uint32_t smem_u32(const void* p) {
    uint32_t a;
    asm("{ .reg .u64 t; cvta.to.shared.u64 t, %1; cvt.u32.u64 %0, t; }" : "=r"(a) : "l"(p));
    return a;
}
__device__ __forceinline__ void mma_f16(float* d, const uint32_t* a, uint32_t b0, uint32_t b1) {
    asm volatile(
        "mma.sync.aligned.m16n8k16.row.col.f32.f16.f16.f32 "
        "{%0,%1,%2,%3}, {%4,%5,%6,%7}, {%8,%9}, {%0,%1,%2,%3};\n"
        : "+f"(d[0]), "+f"(d[1]), "+f"(d[2]), "+f"(d[3])
        : "r"(a[0]), "r"(a[1]), "r"(a[2]), "r"(a[3]), "r"(b0), "r"(b1));
}
#define LDSM_X4(r, addr) \
    asm volatile("ldmatrix.sync.aligned.m8n8.x4.shared.b16 {%0,%1,%2,%3}, [%4];" \
        : "=r"((r)[0]), "=r"((r)[1]), "=r"((r)[2]), "=r"((r)[3]) : "r"(addr))
#define LDSM_X4_T(r, addr) \
    asm volatile("ldmatrix.sync.aligned.m8n8.x4.trans.shared.b16 {%0,%1,%2,%3}, [%4];" \
        : "=r"((r)[0]), "=r"((r)[1]), "=r"((r)[2]), "=r"((r)[3]) : "r"(addr))
#define CP_ASYNC16(dst, src) \
    asm volatile("cp.async.cg.shared.global [%0], [%1], 16;\n" :: "r"(dst), "l"(src))
#define CP_COMMIT() asm volatile("cp.async.commit_group;\n" ::: "memory")
#define CP_WAIT1()  asm volatile("cp.async.wait_group 1;\n" ::: "memory")
#define CP_WAIT0()  asm volatile("cp.async.wait_group 0;\n" ::: "memory")

__device__ __forceinline__ uint32_t packh2(float lo, float hi) {
    __half2 h = __floats2half2_rn(lo, hi);
    return *(uint32_t*)&h;
}

// ---------------- fp32 -> fp16 conversion (8 elems/thread) ------------------
__global__ __launch_bounds__(256) void f2h_kernel(
    const float* __restrict__ src, __half* __restrict__ dst, size_t n8)
{
    size_t i = (size_t)blockIdx.x * 256 + threadIdx.x;
    if (i >= n8) return;
    float4 a = ((const float4*)src)[2 * i];
    float4 b = ((const float4*)src)[2 * i + 1];
    uint4 u;
    u.x = packh2(a.x, a.y); u.y = packh2(a.z, a.w);
    u.z = packh2(b.x, b.y); u.w = packh2(b.z, b.w);
    ((uint4*)dst)[i] = u;
}

// ---------------- merged weight conversion (segmented, one launch) ----------
__global__ __launch_bounds__(256) void wcvt_kernel(
    const float* __restrict__ Wb1, const float* __restrict__ Wb2,
    const float* __restrict__ Ws1, const float* __restrict__ We1,
    const float* __restrict__ We2,
    __half* __restrict__ oWb1, __half* __restrict__ oWb2,
    __half* __restrict__ oWs1, __half* __restrict__ oWe1,
    __half* __restrict__ oWe2)
{
    size_t i = (size_t)blockIdx.x * 256 + threadIdx.x;   // 8-elem chunk id
    const float* s; __half* d; size_t off;
    if (i < 131072)      { s = Wb1; d = oWb1; off = i; }
    else if (i < 196608) { s = Wb2; d = oWb2; off = i - 131072; }
    else if (i < 200704) { s = Ws1; d = oWs1; off = i - 196608; }
    else if (i < 462848) { s = We1; d = oWe1; off = i - 200704; }
    else if (i < 479232) { s = We2; d = oWe2; off = i - 462848; }
    else return;
    float4 a = ((const float4*)s)[2 * off];
    float4 b = ((const float4*)s)[2 * off + 1];
    uint4 u;
    u.x = packh2(a.x, a.y); u.y = packh2(a.z, a.w);
    u.z = packh2(b.x, b.y); u.w = packh2(b.z, b.w);
    ((uint4*)d)[off] = u;
}

// ---------------- concat-convert: W0cat = [Wb0 | Ws0] fp16, b0cat -----------
__global__ __launch_bounds__(256) void cat_kernel(
    const float* __restrict__ Wb0, const float* __restrict__ Ws0,
    const float* __restrict__ bb0, const float* __restrict__ bs0,
    __half* __restrict__ Wcat, float* __restrict__ bcat)
{
    size_t i = (size_t)blockIdx.x * 256 + threadIdx.x;
    if (i < (size_t)512 * 1280) {
        int k = (int)(i / 1280), c = (int)(i % 1280);
        float v = (c < 1024) ? Wb0[(size_t)k * 1024 + c] : Ws0[(size_t)k * 256 + (c - 1024)];
        Wcat[i] = __float2half_rn(v);
    }
    if (i < 1280) bcat[i] = (i < 1024) ? bb0[i] : bs0[i - 1024];
}

// ---------------- generic GEMM: C(half) = act(A @ B + bias) -----------------
// 128 x 128 block, 128 thr, 4 warps (2x2), warp tile 64x64, BK=32.
// 3-stage cp.async pipeline, hoisted ldmatrix, 2 CTAs/SM. (R9 proven config)
template<bool RELU>
__global__ __launch_bounds__(128, 2) void tc_gemm(
    const __half* __restrict__ A, const __half* __restrict__ B,
    const float* __restrict__ bias, __half* __restrict__ C,
    int K, int N, int lda)
{
    extern __shared__ char smem[];
    constexpr int BN  = 128;
    constexpr int RSB = BN * 2 + 16;           // 272
    constexpr int ASZ = 128 * RSA;             // 10240
    constexpr int STG = ASZ + 32 * RSB;        // 18944
    constexpr int NF  = 8;
    float* sbias = (float*)(smem + 3 * STG);

    const int tid = threadIdx.x, warp = tid >> 5, lane = tid & 31;
    const int rA = (warp >> 1) * 64, cB = (warp & 1) * 64;
    const int lg = lane >> 2, lt = lane & 3;
    const int m0 = blockIdx.y * 128, n0 = blockIdx.x * BN;

    const __half* Bp = B + n0;

    if (tid < BN) sbias[tid] = bias[n0 + tid];

    const uint32_t smb = smem_u32(smem);
    const int li = lane & 7, ls = lane >> 3;
    const uint32_t aOff = (uint32_t)(rA + li + 8 * (ls & 1)) * RSA + (ls >> 1) * 16;
    const uint32_t bOff = ASZ + (uint32_t)(li + 8 * (ls & 1)) * RSB
                        + (uint32_t)(cB + 8 * (ls >> 1)) * 2;

    float acc[4][NF][4];
#pragma unroll
    for (int i = 0; i < 4; i++)
#pragma unroll
        for (int j = 0; j < NF; j++)
#pragma unroll
            for (int k = 0; k < 4; k++) acc[i][j][k] = 0.f;

    const int NT = K >> 5;

#define LOAD_STAGE(t, buf)                                                     \
    {                                                                          \
        const uint32_t base = smb + (buf) * STG;                               \
        const int k0 = (t) * 32;                                               \
        _Pragma("unroll")                                                      \
        for (int j = 0; j < 4; j++) {                                          \
            int i = tid + 128 * j;                                             \
            int r = i >> 2, q = i & 3;                                         \
            CP_ASYNC16(base + r * RSA + q * 16,                                \
                       A + (size_t)(m0 + r) * lda + k0 + q * 8);               \
        }                                                                      \
        _Pragma("unroll")                                                      \
        for (int j = 0; j < 4; j++) {                                          \
            int i = tid + 128 * j;                                             \
            int krow = i >> 4, c16 = i & 15;                                   \
            CP_ASYNC16(base + ASZ + krow * RSB + c16 * 16,                     \
                       Bp + (size_t)(k0 + krow) * N + c16 * 8);                \
        }                                                                      \
        CP_COMMIT();                                                           \
    }

    LOAD_STAGE(0, 0);
    LOAD_STAGE(1, 1);

    int buf = 0, nbuf = 2;
    for (int t = 0; t < NT; t++) {
        if (t + 1 < NT) { CP_WAIT1(); } else { CP_WAIT0(); }
        __syncthreads();
        if (t + 2 < NT) { LOAD_STAGE(t + 2, nbuf); }

        const uint32_t base = smb + buf * STG;
        uint32_t a[2][4][4];
        uint32_t b[2][NF / 2][4];
#pragma unroll
        for (int h = 0; h < 2; h++) {
#pragma unroll
            for (int mf = 0; mf < 4; mf++)
                LDSM_X4(a[h][mf], base + aOff + mf * (16 * RSA) + h * 32);
#pragma unroll
            for (int nfp = 0; nfp < NF / 2; nfp++)
                LDSM_X4_T(b[h][nfp], base + bOff + nfp * 32 + h * (16 * RSB));
        }
#pragma unroll
        for (int h = 0; h < 2; h++)
#pragma unroll
            for (int mf = 0; mf < 4; mf++)
#pragma unroll
                for (int nf = 0; nf < NF; nf++)
                    mma_f16(acc[mf][nf], a[h][mf],
                            b[h][nf >> 1][(nf & 1) * 2], b[h][nf >> 1][(nf & 1) * 2 + 1]);
        buf = (buf == 2) ? 0 : buf + 1;
        nbuf = (nbuf == 2) ? 0 : nbuf + 1;
    }
#undef LOAD_STAGE

#pragma unroll
    for (int mf = 0; mf < 4; mf++) {
        int row = m0 + rA + mf * 16 + lg;
#pragma unroll
        for (int nf = 0; nf < NF; nf++) {
            int cl = cB + nf * 8 + lt * 2;
            int col = n0 + cl;
            float b0 = sbias[cl], b1 = sbias[cl + 1];
            float v0 = acc[mf][nf][0] + b0, v1 = acc[mf][nf][1] + b1;
            float v2 = acc[mf][nf][2] + b0, v3 = acc[mf][nf][3] + b1;
            if (RELU) {
                v0 = fmaxf(v0, 0.f); v1 = fmaxf(v1, 0.f);
                v2 = fmaxf(v2, 0.f); v3 = fmaxf(v3, 0.f);
            }
            *(uint32_t*)(C + (size_t)row * N + col)       = packh2(v0, v1);
            *(uint32_t*)(C + (size_t)(row + 8) * N + col) = packh2(v2, v3);
        }
    }
}

// ---------------- fused s1-GEMM + selector + rb -----------------------------
// Per block (m0 = blockIdx.y*128): s1 = relu(s0 @ Ws1 + bs1) kept in SMEM,
// then thread-per-row: logits = s1 @ Ws2 + bs2, softmax -> w, rb = w @ be2.
__global__ __launch_bounds__(128, 2) void selector_fused(
    const __half* __restrict__ A,      // h0s0 + 1024 (s0), lda = 1280
    const __half* __restrict__ B,      // Ws1h [256,128]
    const float* __restrict__ bs1,
    const float* __restrict__ Ws2,     // fp32 [128,16]
    const float* __restrict__ bs2,
    const float* __restrict__ be2,     // fp32 [16,32]
    float* __restrict__ wout, float* __restrict__ rbout)
{
    extern __shared__ char smem[];
    constexpr int BN  = 128, K = 256, LDA = 1280;
    constexpr int RSB = 272;
    constexpr int ASZ = 128 * RSA;
    constexpr int STG = ASZ + 32 * RSB;        // 18944
    constexpr int NF  = 8;
    constexpr int RS1 = 260;                   // s1 smem row stride (bytes)
    constexpr int S1B = 0;                     // s1 tile: 128*260 = 33280
    constexpr int W2O = 33280;                 // Ws2 fp32: 8192 B
    constexpr int BS2O = W2O + 8192;           // bs2: 64 B
    constexpr int BE2O = BS2O + 64;            // be2: 2048 B (ends 43584 < 3*STG)
    float* sbias = (float*)(smem + 3 * STG);

    const int tid = threadIdx.x, warp = tid >> 5, lane = tid & 31;
    const int rA = (warp >> 1) * 64, cB = (warp & 1) * 64;
    const int lg = lane >> 2, lt = lane & 3;
    const int m0 = blockIdx.y * 128;

    if (tid < BN) sbias[tid] = bs1[tid];

    const uint32_t smb = smem_u32(smem);
    const int li = lane & 7, ls = lane >> 3;
    const uint32_t aOff = (uint32_t)(rA + li + 8 * (ls & 1)) * RSA + (ls >> 1) * 16;
    const uint32_t bOff = ASZ + (uint32_t)(li + 8 * (ls & 1)) * RSB
                        + (uint32_t)(cB + 8 * (ls >> 1)) * 2;

    float acc[4][NF][4];
#pragma unroll
    for (int i = 0; i < 4; i++)
#pragma unroll
        for (int j = 0; j < NF; j++)
#pragma unroll
            for (int k = 0; k < 4; k++) acc[i][j][k] = 0.f;

    const int NT = K >> 5;   // 8

#define LOAD_STAGE(t, buf)                                                     \
    {                                                                          \
        const uint32_t base = smb + (buf) * STG;                               \
        const int k0 = (t) * 32;                                               \
        _Pragma("unroll")                                                      \
        for (int j = 0; j < 4; j++) {                                          \
            int i = tid + 128 * j;                                             \
            int r = i >> 2, q = i & 3;                                         \
            CP_ASYNC16(base + r * RSA + q * 16,                                \
                       A + (size_t)(m0 + r) * LDA + k0 + q * 8);               \
        }                                                                      \
        _Pragma("unroll")                                                      \
        for (int j = 0; j < 4; j++) {                                          \
            int i = tid + 128 * j;                                             \
            int krow = i >> 4, c16 = i & 15;                                   \
            CP_ASYNC16(base + ASZ + krow * RSB + c16 * 16,                     \
                       B + (size_t)(k0 + krow) * BN + c16 * 8);                \
        }                                                                      \
        CP_COMMIT();                                                           \
    }

    LOAD_STAGE(0, 0);
    LOAD_STAGE(1, 1);

    int buf = 0, nbuf = 2;
    for (int t = 0; t < NT; t++) {
        if (t + 1 < NT) { CP_WAIT1(); } else { CP_WAIT0(); }
        __syncthreads();
        if (t + 2 < NT) { LOAD_STAGE(t + 2, nbuf); }

        const uint32_t base = smb + buf * STG;
        uint32_t a[2][4][4];
        uint32_t b[2][NF / 2][4];
#pragma unroll
        for (int h = 0; h < 2; h++) {
#pragma unroll
            for (int mf = 0; mf < 4; mf++)
                LDSM_X4(a[h][mf], base + aOff + mf * (16 * RSA) + h * 32);
#pragma unroll
            for (int nfp = 0; nfp < NF / 2; nfp++)
                LDSM_X4_T(b[h][nfp], base + bOff + nfp * 32 + h * (16 * RSB));
        }
#pragma unroll
        for (int h = 0; h < 2; h++)
#pragma unroll
            for (int mf = 0; mf < 4; mf++)
#pragma unroll
                for (int nf = 0; nf < NF; nf++)
                    mma_f16(acc[mf][nf], a[h][mf],
                            b[h][nf >> 1][(nf & 1) * 2], b[h][nf >> 1][(nf & 1) * 2 + 1]);
        buf = (buf == 2) ? 0 : buf + 1;
        nbuf = (nbuf == 2) ? 0 : nbuf + 1;
    }
#undef LOAD_STAGE

    __syncthreads();   // s1 buffer overlays stage buffers

    // ---- epilogue: bias + relu -> s1 fp16 tile in smem ----
#pragma unroll
    for (int mf = 0; mf < 4; mf++) {
        int lr0 = rA + mf * 16 + lg;
#pragma unroll
        for (int nf = 0; nf < NF; nf++) {
            int cl = cB + nf * 8 + lt * 2;
            float b0 = sbias[cl], b1 = sbias[cl + 1];
            float v0 = fmaxf(acc[mf][nf][0] + b0, 0.f);
            float v1 = fmaxf(acc[mf][nf][1] + b1, 0.f);
            float v2 = fmaxf(acc[mf][nf][2] + b0, 0.f);
            float v3 = fmaxf(acc[mf][nf][3] + b1, 0.f);
            *(uint32_t*)(smem + S1B + lr0 * RS1 + cl * 2)       = packh2(v0, v1);
            *(uint32_t*)(smem + S1B + (lr0 + 8) * RS1 + cl * 2) = packh2(v2, v3);
        }
    }
    // ---- load Ws2 / bs2 / be2 into smem (disjoint from s1 region) ----
    {
        float* W2s = (float*)(smem + W2O);
        for (int i = tid; i < 2048; i += 128) W2s[i] = Ws2[i];
        float* b2s = (float*)(smem + BS2O);
        if (tid < 16) b2s[tid] = bs2[tid];
        float* be2s = (float*)(smem + BE2O);
        for (int i = tid; i < 512; i += 128) be2s[i] = be2[i];
    }
    __syncthreads();

    // ---- thread-per-row: logits + softmax + rb ----
    {
        const int row = m0 + tid;
        const __half2* s1r = (const __half2*)(smem + S1B + tid * RS1);
        const float* W2s = (const float*)(smem + W2O);
        const float* b2s = (const float*)(smem + BS2O);
        const float* be2s = (const float*)(smem + BE2O);

        float logit[16];
#pragma unroll
        for (int e = 0; e < 16; e++) logit[e] = b2s[e];
#pragma unroll 4
        for (int k2 = 0; k2 < 64; k2++) {
            float2 sv = __half22float2(s1r[k2]);
#pragma unroll
            for (int e = 0; e < 16; e++)
                logit[e] += sv.x * W2s[(2 * k2) * 16 + e] + sv.y * W2s[(2 * k2 + 1) * 16 + e];
        }
        float m = logit[0];
#pragma unroll
        for (int e = 1; e < 16; e++) m = fmaxf(m, logit[e]);
        float ex[16], ssum = 0.f;
#pragma unroll
        for (int e = 0; e < 16; e++) { ex[e] = __expf(logit[e] - m); ssum += ex[e]; }
        float wv[16];
#pragma unroll
        for (int e = 0; e < 16; e++) {
            wv[e] = ex[e] / ssum;
            wout[(size_t)row * 16 + e] = wv[e];
        }
#pragma unroll
        for (int a4 = 0; a4 < 8; a4++) {
            float4 r;
            float* rp = (float*)&r;
#pragma unroll
            for (int q = 0; q < 4; q++) {
                float s = 0.f;
#pragma unroll
                for (int e = 0; e < 16; e++) s += wv[e] * be2s[e * 32 + a4 * 4 + q];
                rp[q] = s;
            }
            *(float4*)(rbout + (size_t)row * 32 + a4 * 4) = r;
        }
    }
}

// ---------------- fused expert kernel (R9 proven shape: 256 thr, BN=256) ----
__global__ __launch_bounds__(256, 1) void expert_gemm(
    const __half* __restrict__ A, const __half* __restrict__ We1,
    const float* __restrict__ be1, const float* __restrict__ wsel,
    const __half* __restrict__ We2, float* __restrict__ part)
{
    extern __shared__ char smem[];
    constexpr int BN = 256, K = 512;
    constexpr int RSB = BN * 2 + 16;
    constexpr int ASZ = 128 * RSA;
    constexpr int STG = ASZ + 32 * RSB;
    constexpr int CPR = BN / 8;
    constexpr int NF  = 8;
    constexpr int GBUF = 0;
    constexpr int W2S  = 128 * RSG;
    float* sbias = (float*)(smem + 3 * STG);

    const int tid = threadIdx.x, warp = tid >> 5, lane = tid & 31;
    const int rA = (warp >> 2) * 64, cB = (warp & 3) * 64;
    const int lg = lane >> 2, lt = lane & 3;
    const int m0 = blockIdx.y * 128;
    const int e  = blockIdx.x;

    const __half* Bp = We1 + (size_t)e * K * 256;

    for (int i = tid; i < BN; i += 256) sbias[i] = be1[e * 256 + i];

    const uint32_t smb = smem_u32(smem);
    const int li = lane & 7, ls = lane >> 3;
    const uint32_t aOff = (uint32_t)(rA + li + 8 * (ls & 1)) * RSA + (ls >> 1) * 16;
    const uint32_t bOff = ASZ + (uint32_t)(li + 8 * (ls & 1)) * RSB
                        + (uint32_t)(cB + 8 * (ls >> 1)) * 2;

    float acc[4][NF][4];
#pragma unroll
    for (int i = 0; i < 4; i++)
#pragma unroll
        for (int j = 0; j < NF; j++)
#pragma unroll
            for (int k = 0; k < 4; k++) acc[i][j][k] = 0.f;

    const int NT = K >> 5;

#define LOAD_STAGE(t, bufi)                                                    \
    {                                                                          \
        const uint32_t base = smb + (bufi) * STG;                              \
        const int k0 = (t) * 32;                                               \
        _Pragma("unroll")                                                      \
        for (int j = 0; j < 2; j++) {                                          \
            int i = tid + 256 * j;                                             \
            int r = i >> 2, q = i & 3;                                         \
            CP_ASYNC16(base + r * RSA + q * 16,                                \
                       A + (size_t)(m0 + r) * K + k0 + q * 8);                 \
        }                                                                      \
        _Pragma("unroll")                                                      \
        for (int j = 0; j < 4; j++) {                                          \
            int i = tid + 256 * j;                                             \
            int krow = i / CPR, c16 = i % CPR;                                 \
            CP_ASYNC16(base + ASZ + krow * RSB + c16 * 16,                     \
                       Bp + (size_t)(k0 + krow) * 256 + c16 * 8);              \
        }                                                                      \
        CP_COMMIT();                                                           \
    }

    LOAD_STAGE(0, 0);
    LOAD_STAGE(1, 1);

    int buf = 0, nbuf = 2;
    for (int t = 0; t < NT; t++) {
        if (t + 1 < NT) { CP_WAIT1(); } else { CP_WAIT0(); }
        __syncthreads();
        if (t + 2 < NT) { LOAD_STAGE(t + 2, nbuf); }

        const uint32_t base = smb + buf * STG;
        uint32_t a[2][4][4];
        uint32_t b[2][4][4];
#pragma unroll
        for (int h = 0; h < 2; h++) {
#pragma unroll
            for (int mf = 0; mf < 4; mf++)
                LDSM_X4(a[h][mf], base + aOff + mf * (16 * RSA) + h * 32);
#pragma unroll
            for (int nfp = 0; nfp < 4; nfp++)
                LDSM_X4_T(b[h][nfp], base + bOff + nfp * 32 + h * (16 * RSB));
        }
#pragma unroll
        for (int h = 0; h < 2; h++)
#pragma unroll
            for (int mf = 0; mf < 4; mf++)
#pragma unroll
                for (int nf = 0; nf < NF; nf++)
                    mma_f16(acc[mf][nf], a[h][mf],
                            b[h][nf >> 1][(nf & 1) * 2], b[h][nf >> 1][(nf & 1) * 2 + 1]);
        buf = (buf == 2) ? 0 : buf + 1;
        nbuf = (nbuf == 2) ? 0 : nbuf + 1;
    }
#undef LOAD_STAGE

    __syncthreads();   // epilogue overlays stage buffers

    // ---- epilogue 1: bias + relu + w-scale, pack g into smem ----
#pragma unroll
    for (int mf = 0; mf < 4; mf++) {
        int row = m0 + rA + mf * 16 + lg;
        int lr0 = rA + mf * 16 + lg;
        float ws0 = wsel[(size_t)row * 16 + e];
        float ws1 = wsel[(size_t)(row + 8) * 16 + e];
#pragma unroll
        for (int nf = 0; nf < NF; nf++) {
            int cl = cB + nf * 8 + lt * 2;
            float b0 = sbias[cl], b1 = sbias[cl + 1];
            float v0 = fmaxf(acc[mf][nf][0] + b0, 0.f) * ws0;
            float v1 = fmaxf(acc[mf][nf][1] + b1, 0.f) * ws0;
            float v2 = fmaxf(acc[mf][nf][2] + b0, 0.f) * ws1;
            float v3 = fmaxf(acc[mf][nf][3] + b1, 0.f) * ws1;
            *(uint32_t*)(smem + GBUF + lr0 * RSG + cl * 2)       = packh2(v0, v1);
            *(uint32_t*)(smem + GBUF + (lr0 + 8) * RSG + cl * 2) = packh2(v2, v3);
        }
    }

    // ---- load We2[e] (256x32 half) into smem ----
#pragma unroll
    for (int j = 0; j < 4; j++) {
        int i = tid + 256 * j;
        int hrow = i >> 2, q = i & 3;
        uint4 u = *(const uint4*)(We2 + ((size_t)e * 256 + hrow) * 32 + q * 8);
        *(uint4*)(smem + W2S + hrow * RSA + q * 16) = u;
    }
    __syncthreads();

    // ---- mini-GEMM: part_tile = g(128x256) @ We2s(256x32) ----
    {
        const uint32_t aAddr2 = smb + GBUF
            + (uint32_t)(warp * 16 + li + 8 * (ls & 1)) * RSG + (ls >> 1) * 16;
        const uint32_t bAddr2 = smb + W2S
            + (uint32_t)(li + 8 * (ls & 1)) * RSA + (uint32_t)(8 * (ls >> 1)) * 2;

        float acc2[4][4];
#pragma unroll
        for (int nf = 0; nf < 4; nf++)
#pragma unroll
            for (int k = 0; k < 4; k++) acc2[nf][k] = 0.f;

#pragma unroll
        for (int ks = 0; ks < 16; ks++) {
            uint32_t a[4];
            LDSM_X4(a, aAddr2 + ks * 32);
            uint32_t b[2][4];
#pragma unroll
            for (int nfp = 0; nfp < 2; nfp++)
                LDSM_X4_T(b[nfp], bAddr2 + nfp * 32 + ks * (16 * RSA));
#pragma unroll
            for (int nf = 0; nf < 4; nf++)
                mma_f16(acc2[nf], a, b[nf >> 1][(nf & 1) * 2], b[nf >> 1][(nf & 1) * 2 + 1]);
        }

        float* P = part + (size_t)e * ((size_t)BATCH * 32);
        int row = m0 + warp * 16 + lg;
#pragma unroll
        for (int nf = 0; nf < 4; nf++) {
            int col = nf * 8 + lt * 2;
            *(float2*)(P + (size_t)row * 32 + col)       = make_float2(acc2[nf][0], acc2[nf][1]);
            *(float2*)(P + (size_t)(row + 8) * 32 + col) = make_float2(acc2[nf][2], acc2[nf][3]);
        }
    }
}

// ---------------- 16-way partial reduce + row-bias --------------------------
__global__ __launch_bounds__(256) void reduce_final(
    const float* __restrict__ part, const float* __restrict__ rb,
    float* __restrict__ out)
{
    size_t idx = (size_t)blockIdx.x * 256 + threadIdx.x;
    const size_t S = (size_t)BATCH * 32 / 4;
    const float4* p4 = (const float4*)part;
    float4 r = ((const float4*)rb)[idx];
#pragma unroll
    for (int s = 0; s < 16; s++) {
        float4 p = p4[s * S + idx];
        r.x += p.x; r.y += p.y; r.z += p.z; r.w += p.w;
    }
    ((float4*)out)[idx] = r;
}

// ---------------- launch -----------------------------------------------------
extern "C" void kernel_launch(void* const* d_in, const int* in_sizes, int n_in,
                              void* d_out, int out_size)
{
    const float* obs = (const float*)d_in[0];
    const float* Wb0 = (const float*)d_in[1];  const float* bb0 = (const float*)d_in[2];
    const float* Wb1 = (const float*)d_in[3];  const float* bb1 = (const float*)d_in[4];
    const float* Wb2 = (const float*)d_in[5];  const float* bb2 = (const float*)d_in[6];
    const float* We1 = (const float*)d_in[7];  const float* be1 = (const float*)d_in[8];
    const float* We2 = (const float*)d_in[9];  const float* be2 = (const float*)d_in[10];
    const float* Ws0 = (const float*)d_in[11]; const float* bs0 = (const float*)d_in[12];
    const float* Ws1 = (const float*)d_in[13]; const float* bs1 = (const float*)d_in[14];
    const float* Ws2 = (const float*)d_in[15]; const float* bs2 = (const float*)d_in[16];
    float* out = (float*)d_out;

    __half *obsh, *h0s0, *h1, *h2;
    __half *W0cat, *Wb1h, *Wb2h, *Ws1h, *We1h, *We2h;
    float *b0cat, *w, *rb, *part;
    cudaGetSymbolAddress((void**)&obsh, g_obsh);
    cudaGetSymbolAddress((void**)&h0s0, g_h0s0);
    cudaGetSymbolAddress((void**)&h1, g_h1);
    cudaGetSymbolAddress((void**)&h2, g_h2);
    cudaGetSymbolAddress((void**)&w,  g_w);
    cudaGetSymbolAddress((void**)&rb, g_rb);
    cudaGetSymbolAddress((void**)&part, g_part);
    cudaGetSymbolAddress((void**)&W0cat, g_W0cat);
    cudaGetSymbolAddress((void**)&b0cat, g_b0cat);
    cudaGetSymbolAddress((void**)&Wb1h, g_Wb1h);
    cudaGetSymbolAddress((void**)&Wb2h, g_Wb2h);
    cudaGetSymbolAddress((void**)&Ws1h, g_Ws1h);
    cudaGetSymbolAddress((void**)&We1h, g_We1h);
    cudaGetSymbolAddress((void**)&We2h, g_We2h);

    constexpr int STG = 128 * RSA + 32 * 272;               // 18944
    constexpr int SMG = 3 * STG + 512;                      // 57344 (2 CTAs/SM)
    cudaFuncSetAttribute((const void*)tc_gemm<true>,
                         cudaFuncAttributeMaxDynamicSharedMemorySize, SMG);
    cudaFuncSetAttribute((const void*)selector_fused,
                         cudaFuncAttributeMaxDynamicSharedMemorySize, SMG);
    cudaFuncSetAttribute((const void*)expert_gemm,
                         cudaFuncAttributeMaxDynamicSharedMemorySize, 90112);

    // conversions: obs (large), W0cat, all other weights in ONE launch
    {
        size_t n8 = (size_t)BATCH * 512 / 8;
        f2h_kernel<<<(unsigned)((n8 + 255) / 256), 256>>>(obs, obsh, n8);
    }
    cat_kernel<<<(512 * 1280 + 255) / 256, 256>>>(Wb0, Ws0, bb0, bs0, W0cat, b0cat);
    wcvt_kernel<<<(479232 + 255) / 256, 256>>>(Wb1, Wb2, Ws1, We1, We2,
                                               Wb1h, Wb2h, Ws1h, We1h, We2h);

    const int MB = BATCH / 128;   // 512

    // fused backbone-L0 + selector-S0: [B,512] @ [512,1280] -> [h0 | s0]
    tc_gemm<true><<<dim3(10, MB), 128, SMG>>>(obsh, W0cat, b0cat, h0s0, 512, 1280, 512);

    // fused selector: s1 GEMM + softmax + rb in one kernel
    selector_fused<<<dim3(1, MB), 128, SMG>>>(h0s0 + 1024, Ws1h, bs1,
                                              Ws2, bs2, be2, w, rb);

    // backbone
    tc_gemm<true><<<dim3(8, MB), 128, SMG>>>(h0s0, Wb1h, bb1, h1, 1024, 1024, 1280);
    tc_gemm<true><<<dim3(4, MB), 128, SMG>>>(h1, Wb2h, bb2, h2, 1024, 512, 1024);

    // fused experts (R9 proven shape)
    expert_gemm<<<dim3(16, MB), 256, 90112>>>(h2, We1h, be1, w, We2h, part);

    // final reduce
    reduce_final<<<(BATCH * 32 / 4) / 256, 256>>>(part, rb, out);
}